// round 15
// baseline (speedup 1.0000x reference)
#include <cuda_runtime.h>
#include <math.h>
#include <stdint.h>

// Problem constants
#define NB  2
#define NL  2048
#define ND  1024
#define NH  8
#define NHD 128
#define NZ  (NB*NH)   // 16 batched heads

// ---------------- static device scratch ----------------
__device__ float g_Q[(size_t)NZ * NL * NHD];   // [z][l][j]      (tf32-rounded)
__device__ float g_K[(size_t)NZ * NL * NHD];   // [z][l][j]      (tf32-rounded)
__device__ float g_V[(size_t)NZ * NHD * NL];   // [z][j][l]      (tf32-rounded)
__device__ float g_S[(size_t)NZ * NL * NL];    // scores -> probs (probs tf32-rounded)
__device__ float g_A[(size_t)NB * NL * ND];    // concat attn out (tf32-rounded)
__device__ float g_R[(size_t)NB * NL * ND];    // pre-LN result (fp32)
__device__ float g_WT[(size_t)4 * ND * ND];    // W^T [q,k,v,o]  (tf32-rounded)
__device__ float g_DE[(size_t)NB * NL * ND];   // tf32-rounded de
__device__ float g_EN[(size_t)NB * NL * ND];   // tf32-rounded en
__device__ int   g_mask_flag;                  // 0=int32, 1=byte, 2=float32

// ---------------- tf32 / async-copy helpers (sm_80+ PTX; legal on compute_103) ----
__device__ __forceinline__ uint32_t cvt_tf32(float x) {
    uint32_t u; asm("cvt.rna.tf32.f32 %0, %1;" : "=r"(u) : "f"(x)); return u;
}
__device__ __forceinline__ float rtf(float x) { return __uint_as_float(cvt_tf32(x)); }

__device__ __forceinline__ void mma_tf32(float* d, const uint32_t* a, const uint32_t* b) {
    asm volatile(
        "mma.sync.aligned.m16n8k8.row.col.f32.tf32.tf32.f32 "
        "{%0,%1,%2,%3}, {%4,%5,%6,%7}, {%8,%9}, {%0,%1,%2,%3};"
        : "+f"(d[0]), "+f"(d[1]), "+f"(d[2]), "+f"(d[3])
        : "r"(a[0]), "r"(a[1]), "r"(a[2]), "r"(a[3]), "r"(b[0]), "r"(b[1]));
}
__device__ __forceinline__ uint32_t smem_u32(const void* p) {
    uint32_t a;
    asm("{ .reg .u64 t; cvta.to.shared.u64 t, %1; cvt.u32.u64 %0, t; }" : "=r"(a) : "l"(p));
    return a;
}
__device__ __forceinline__ void cp16(uint32_t d, const void* s) {
    asm volatile("cp.async.cg.shared.global [%0], [%1], 16;" :: "r"(d), "l"(s));
}
__device__ __forceinline__ void cp_commit() { asm volatile("cp.async.commit_group;" ::: "memory"); }
template<int N> __device__ __forceinline__ void cp_wait() {
    asm volatile("cp.async.wait_group %0;" :: "n"(N) : "memory");
}

// ---------------- shared GEMM core v4: occupancy + 4-stage cp.async ----------------
// CTA tile 128x128, BK=16, 256 threads = 8 warps as 2(M) x 4(N); warp tile 64x32.
// acc = 64 regs -> __launch_bounds__(256,2) -> 2 CTAs/SM = 16 warps/SM (4/SMSP):
// 2x issue parallelism vs R14 (which was latency-bound at occ=11.5%).
// 4-stage cp.async pipeline (wait_group<2>): 3 tiles in flight hides tile latency.
// Smem rows padded to LDR=20 floats: conflict-free fragment access (20 mod 32
// stride-permutation covers all 32 banks), 80B rows keep 16B cp.async alignment.
#define LDR 20
#define SM_TILE (128 * LDR)                          // floats per operand per stage
#define NSTG 4
#define GEMM_SMEM (NSTG * 2 * SM_TILE * 4)           // 81920 bytes

__device__ __forceinline__ void gemm_mma(
    const float* __restrict__ A, int lda,
    const float* __restrict__ B, int ldb,
    int K, float acc[4][4][4])
{
    extern __shared__ float sm[];                    // [NSTG][2][SM_TILE]
    const int tid  = threadIdx.x;
    const int lane = tid & 31, wid = tid >> 5;
    const int m0 = (wid & 1) * 64, n0 = (wid >> 1) * 32;
    const int gid = lane >> 2, tq = lane & 3;

    const int r0 = tid >> 1;                         // rows 0..127
    const int c0 = (tid & 1) * 4;                    // float col: c0 and c0+8

    const uint32_t sbase = smem_u32(sm);
    const uint32_t so0 = (uint32_t)((r0 * LDR + c0) * 4);
    const uint32_t so1 = so0 + 32;                   // +8 floats

    #pragma unroll
    for (int mt = 0; mt < 4; mt++)
        #pragma unroll
        for (int nt = 0; nt < 4; nt++)
            #pragma unroll
            for (int r = 0; r < 4; r++) acc[mt][nt][r] = 0.0f;

    auto issue = [&](int t, int s) {
        const float* Ap = A + t * 16 + (size_t)r0 * lda;
        const float* Bp = B + t * 16 + (size_t)r0 * ldb;
        const uint32_t sa = sbase + (uint32_t)(s * 2 * SM_TILE * 4);
        const uint32_t sb = sa + (uint32_t)(SM_TILE * 4);
        cp16(sa + so0, Ap + c0);
        cp16(sa + so1, Ap + c0 + 8);
        cp16(sb + so0, Bp + c0);
        cp16(sb + so1, Bp + c0 + 8);
        cp_commit();
    };

    const int T = K >> 4;
    issue(0, 0);
    if (T > 1) issue(1, 1);
    if (T > 2) issue(2, 2);

    for (int t = 0; t < T; t++) {
        if (t + 3 <= T)      cp_wait<2>();
        else if (t + 2 <= T) cp_wait<1>();
        else                 cp_wait<0>();
        __syncthreads();
        if (t + 3 < T) issue(t + 3, (t + 3) & (NSTG - 1));

        const uint32_t* sAu = (const uint32_t*)(sm + (t & (NSTG - 1)) * 2 * SM_TILE);
        const uint32_t* sBu = sAu + SM_TILE;

        #pragma unroll
        for (int ks = 0; ks < 16; ks += 8) {
            uint32_t af[4][4], bf[4][2];
            #pragma unroll
            for (int mt = 0; mt < 4; mt++) {
                int mr = m0 + mt * 16 + gid;
                af[mt][0] = sAu[mr * LDR + ks + tq];
                af[mt][1] = sAu[(mr + 8) * LDR + ks + tq];
                af[mt][2] = sAu[mr * LDR + ks + tq + 4];
                af[mt][3] = sAu[(mr + 8) * LDR + ks + tq + 4];
            }
            #pragma unroll
            for (int nt = 0; nt < 4; nt++) {
                int nr = n0 + nt * 8 + gid;
                bf[nt][0] = sBu[nr * LDR + ks + tq];
                bf[nt][1] = sBu[nr * LDR + ks + tq + 4];
            }
            #pragma unroll
            for (int mt = 0; mt < 4; mt++)
                #pragma unroll
                for (int nt = 0; nt < 4; nt++)
                    mma_tf32(acc[mt][nt], af[mt], bf[nt]);
        }
    }
}

// epilogue element mapping:
// row = bm + (wid&1)*64 + mt*16 + gid + hh*8 ; col = bn + (wid>>1)*32 + nt*8 + tq*2 + e
// val = acc[mt][nt][hh*2+e]

// ---------------- mask dtype detection ----------------
__global__ void k_detect(const unsigned char* __restrict__ m) {
    __shared__ int f1, f3;
    if (threadIdx.x == 0) { f1 = 0; f3 = 0; }
    __syncthreads();
    int l1 = 0, l3 = 0;
    const uchar4* m4 = reinterpret_cast<const uchar4*>(m);
    for (int i = threadIdx.x; i < 16384; i += 256) { uchar4 c = m4[i]; l1 |= c.y; l3 |= c.w; }
    if (l1) atomicOr(&f1, 1);
    if (l3) atomicOr(&f3, 1);
    __syncthreads();
    if (threadIdx.x == 0) g_mask_flag = f1 ? 1 : (f3 ? 2 : 0);
}

// ---------------- pre-round de/en to tf32 copies ----------------
__global__ void k_round(const float* __restrict__ de, const float* __restrict__ en) {
    size_t i = (size_t)blockIdx.x * blockDim.x + threadIdx.x;   // float4 index
    float4 d = ((const float4*)de)[i];
    d.x = rtf(d.x); d.y = rtf(d.y); d.z = rtf(d.z); d.w = rtf(d.w);
    ((float4*)g_DE)[i] = d;
    float4 e = ((const float4*)en)[i];
    e.x = rtf(e.x); e.y = rtf(e.y); e.z = rtf(e.z); e.w = rtf(e.w);
    ((float4*)g_EN)[i] = e;
}

// ---------------- weight transpose (tf32-rounded): g_WT[z][out][in] ----------------
__global__ void k_transp(const float* __restrict__ W0, const float* __restrict__ W1,
                         const float* __restrict__ W2, const float* __restrict__ W3) {
    __shared__ float t[32][33];
    const int z = blockIdx.z;
    const float* W = (z == 0) ? W0 : (z == 1) ? W1 : (z == 2) ? W2 : W3;
    float* O = g_WT + (size_t)z * ND * ND;
    int x = blockIdx.x * 32 + threadIdx.x;
    #pragma unroll
    for (int j = 0; j < 32; j += 8)
        t[threadIdx.y + j][threadIdx.x] = W[(size_t)(blockIdx.y * 32 + threadIdx.y + j) * ND + x];
    __syncthreads();
    int ox = blockIdx.y * 32 + threadIdx.x;
    #pragma unroll
    for (int j = 0; j < 32; j += 8)
        O[(size_t)(blockIdx.x * 32 + threadIdx.y + j) * ND + ox] = rtf(t[threadIdx.x][threadIdx.y + j]);
}

// ---------------- QKV projections, head-deinterleave epilogue ----------------
__global__ __launch_bounds__(256, 2) void k_qkv_t(
    const float* __restrict__ bq, const float* __restrict__ bk, const float* __restrict__ bv) {
    const int z = blockIdx.z;
    const float* X    = (z == 0) ? g_DE : g_EN;
    const float* bias = (z == 0) ? bq : (z == 1 ? bk : bv);
    const float* WT   = g_WT + (size_t)z * ND * ND;
    const int bm = blockIdx.y * 128, bn = blockIdx.x * 128;

    float acc[4][4][4];
    gemm_mma(X + (size_t)bm * ND, ND, WT + (size_t)bn * ND, ND, ND, acc);

    const int lane = threadIdx.x & 31, wid = threadIdx.x >> 5;
    const int m0 = (wid & 1) * 64, n0 = (wid >> 1) * 32;
    const int gid = lane >> 2, tq = lane & 3;
    float* qdst = (z == 0) ? g_Q : g_K;
    #pragma unroll
    for (int mt = 0; mt < 4; mt++)
        #pragma unroll
        for (int hh = 0; hh < 2; hh++) {
            int m = bm + m0 + mt * 16 + gid + hh * 8;
            int b = m >> 11, l = m & (NL - 1);
            #pragma unroll
            for (int nt = 0; nt < 4; nt++)
                #pragma unroll
                for (int e = 0; e < 2; e++) {
                    int n = bn + n0 + nt * 8 + tq * 2 + e;
                    float val = rtf(acc[mt][nt][hh * 2 + e] + bias[n]);   // tf32 for next GEMM
                    int h = n & 7, jj = n >> 3;    // interleaved split: feature = jj*8+h
                    if (z < 2) qdst[(((size_t)(b * NH + h) * NL + l) << 7) + jj] = val;
                    else       g_V[((size_t)(b * NH + h) * NHD + jj) * NL + l] = val;  // V^T
                }
        }
}

// ---------------- S = Q K^T / 32, masked ----------------
__global__ __launch_bounds__(256, 2) void k_qk_t(const unsigned char* __restrict__ maskraw) {
    const int z = blockIdx.z, b = z >> 3;
    const int bm = blockIdx.y * 128, bn = blockIdx.x * 128;
    const float* Qb = g_Q + (size_t)z * NL * NHD;
    const float* Kb = g_K + (size_t)z * NL * NHD;

    float acc[4][4][4];
    gemm_mma(Qb + (size_t)bm * NHD, NHD, Kb + (size_t)bn * NHD, NHD, NHD, acc);

    const int lane = threadIdx.x & 31, wid = threadIdx.x >> 5;
    const int m0 = (wid & 1) * 64, n0 = (wid >> 1) * 32;
    const int gid = lane >> 2, tq = lane & 3;
    const int mf = g_mask_flag;
    #pragma unroll
    for (int mt = 0; mt < 4; mt++)
        #pragma unroll
        for (int hh = 0; hh < 2; hh++) {
            int m = bm + m0 + mt * 16 + gid + hh * 8;
            const size_t mrow = ((size_t)b * NL + m) * NL;
            float* srow = g_S + ((size_t)z * NL + m) * NL;
            #pragma unroll
            for (int nt = 0; nt < 4; nt++) {
                int n = bn + n0 + nt * 8 + tq * 2;
                float v0 = acc[mt][nt][hh * 2 + 0] * 0.03125f;   // 1/sqrt(1024)
                float v1 = acc[mt][nt][hh * 2 + 1] * 0.03125f;
                bool k0, k1;
                if (mf == 1) {
                    const unsigned char* mp = maskraw + mrow + n;
                    k0 = mp[0] != 0; k1 = mp[1] != 0;
                } else if (mf == 2) {
                    const float* mp = (const float*)maskraw + mrow + n;
                    k0 = mp[0] != 0.0f; k1 = mp[1] != 0.0f;
                } else {
                    const int* mp = (const int*)maskraw + mrow + n;
                    k0 = mp[0] != 0; k1 = mp[1] != 0;
                }
                float2 o;
                o.x = k0 ? -1e10f : v0;
                o.y = k1 ? -1e10f : v1;
                *(float2*)(srow + n) = o;
            }
        }
}

// ---------------- O = P V, concat-layout epilogue (tf32-rounded for k_out) ------
__global__ __launch_bounds__(256, 2) void k_pv_t() {
    const int z = blockIdx.z, b = z >> 3, h = z & 7;
    const int bm = blockIdx.y * 128;
    const float* P  = g_S + (size_t)z * NL * NL + (size_t)bm * NL;
    const float* Vt = g_V + (size_t)z * NHD * NL;        // [j][l], ld = NL

    float acc[4][4][4];
    gemm_mma(P, NL, Vt, NL, NL, acc);

    const int lane = threadIdx.x & 31, wid = threadIdx.x >> 5;
    const int m0 = (wid & 1) * 64, n0 = (wid >> 1) * 32;
    const int gid = lane >> 2, tq = lane & 3;
    #pragma unroll
    for (int mt = 0; mt < 4; mt++)
        #pragma unroll
        for (int hh = 0; hh < 2; hh++) {
            int m = bm + m0 + mt * 16 + gid + hh * 8;
            float* arow = g_A + ((size_t)b * NL + m) * ND + h * NHD;
            #pragma unroll
            for (int nt = 0; nt < 4; nt++) {
                int n = n0 + nt * 8 + tq * 2;
                float2 o;
                o.x = rtf(acc[mt][nt][hh * 2 + 0]);
                o.y = rtf(acc[mt][nt][hh * 2 + 1]);
                *(float2*)(arow + n) = o;
            }
        }
}

// ---------------- R = A Wo + bo + de (residual, fp32 out) ----------------
__global__ __launch_bounds__(256, 2) void k_out_t(const float* __restrict__ bo,
                                                  const float* __restrict__ de) {
    const int bm = blockIdx.y * 128, bn = blockIdx.x * 128;
    const float* WoT = g_WT + (size_t)3 * ND * ND;

    float acc[4][4][4];
    gemm_mma(g_A + (size_t)bm * ND, ND, WoT + (size_t)bn * ND, ND, ND, acc);

    const int lane = threadIdx.x & 31, wid = threadIdx.x >> 5;
    const int m0 = (wid & 1) * 64, n0 = (wid >> 1) * 32;
    const int gid = lane >> 2, tq = lane & 3;
    #pragma unroll
    for (int mt = 0; mt < 4; mt++)
        #pragma unroll
        for (int hh = 0; hh < 2; hh++) {
            int m = bm + m0 + mt * 16 + gid + hh * 8;
            const float* drow = de + (size_t)m * ND;
            float* rrow = g_R + (size_t)m * ND;
            #pragma unroll
            for (int nt = 0; nt < 4; nt++) {
                int n = bn + n0 + nt * 8 + tq * 2;
                float2 d2 = *(const float2*)(drow + n);
                float2 b2 = *(const float2*)(bo + n);
                float2 o;
                o.x = acc[mt][nt][hh * 2 + 0] + b2.x + d2.x;
                o.y = acc[mt][nt][hh * 2 + 1] + b2.y + d2.y;
                *(float2*)(rrow + n) = o;
            }
        }
}

// ---------------- block-wide allreduce ----------------
__device__ __forceinline__ float blockAllReduce(float v, bool doMax) {
    __shared__ float sh[8];
    __shared__ float res;
    #pragma unroll
    for (int o = 16; o; o >>= 1) {
        float t = __shfl_xor_sync(0xffffffffu, v, o);
        v = doMax ? fmaxf(v, t) : (v + t);
    }
    if ((threadIdx.x & 31) == 0) sh[threadIdx.x >> 5] = v;
    __syncthreads();
    if (threadIdx.x < 32) {
        float t = (threadIdx.x < 8) ? sh[threadIdx.x] : (doMax ? -INFINITY : 0.0f);
        #pragma unroll
        for (int o = 4; o; o >>= 1) {
            float u = __shfl_xor_sync(0xffffffffu, t, o);
            t = doMax ? fmaxf(t, u) : (t + u);
        }
        if (threadIdx.x == 0) res = t;
    }
    __syncthreads();
    return res;
}

// ---------------- row softmax over S (in place; probs tf32-rounded) ----------------
__global__ __launch_bounds__(256) void k_softmax() {
    size_t row = blockIdx.x;
    float4* p = reinterpret_cast<float4*>(g_S) + row * (NL / 4);
    float4 a = p[threadIdx.x];
    float4 c = p[threadIdx.x + 256];
    float m = fmaxf(fmaxf(fmaxf(a.x, a.y), fmaxf(a.z, a.w)),
                    fmaxf(fmaxf(c.x, c.y), fmaxf(c.z, c.w)));
    m = blockAllReduce(m, true);
    a.x = __expf(a.x - m); a.y = __expf(a.y - m); a.z = __expf(a.z - m); a.w = __expf(a.w - m);
    c.x = __expf(c.x - m); c.y = __expf(c.y - m); c.z = __expf(c.z - m); c.w = __expf(c.w - m);
    float s = a.x + a.y + a.z + a.w + c.x + c.y + c.z + c.w;
    s = blockAllReduce(s, false);
    float inv = 1.0f / s;
    a.x = rtf(a.x * inv); a.y = rtf(a.y * inv); a.z = rtf(a.z * inv); a.w = rtf(a.w * inv);
    c.x = rtf(c.x * inv); c.y = rtf(c.y * inv); c.z = rtf(c.z * inv); c.w = rtf(c.w * inv);
    p[threadIdx.x] = a;
    p[threadIdx.x + 256] = c;
}

// ---------------- LayerNorm (ddof=1, eps=1e-8, scalar gamma/beta) ----------------
__global__ __launch_bounds__(256) void k_ln(
    float* __restrict__ out, const float* __restrict__ gamma, const float* __restrict__ beta) {
    size_t row = blockIdx.x;
    const float4* x4 = reinterpret_cast<const float4*>(g_R) + row * (ND / 4);
    float4 v = x4[threadIdx.x];
    float s  = v.x + v.y + v.z + v.w;
    float ss = v.x * v.x + v.y * v.y + v.z * v.z + v.w * v.w;
    s  = blockAllReduce(s,  false);
    ss = blockAllReduce(ss, false);
    float mu  = s * (1.0f / 1024.0f);
    float var = (ss - 1024.0f * mu * mu) * (1.0f / 1023.0f);
    float w = rsqrtf(var + 1e-8f);
    float g = gamma[0] * w, bb = beta[0];
    float4 o;
    o.x = (v.x - mu) * g + bb;
    o.y = (v.y - mu) * g + bb;
    o.z = (v.z - mu) * g + bb;
    o.w = (v.w - mu) * g + bb;
    reinterpret_cast<float4*>(out)[row * (ND / 4) + threadIdx.x] = o;
}

// ---------------- launch ----------------
extern "C" void kernel_launch(void* const* d_in, const int* in_sizes, int n_in,
                              void* d_out, int out_size) {
    (void)in_sizes; (void)n_in; (void)out_size;
    const float* en = (const float*)d_in[0];
    const float* de = (const float*)d_in[1];
    const unsigned char* mask = (const unsigned char*)d_in[2];
    const float* Wq = (const float*)d_in[3];
    const float* bq = (const float*)d_in[4];
    const float* Wk = (const float*)d_in[5];
    const float* bk = (const float*)d_in[6];
    const float* Wv = (const float*)d_in[7];
    const float* bv = (const float*)d_in[8];
    const float* Wo = (const float*)d_in[9];
    const float* bo = (const float*)d_in[10];
    const float* gamma = (const float*)d_in[11];
    const float* beta  = (const float*)d_in[12];
    float* out = (float*)d_out;

    static bool attr_done = false;
    if (!attr_done) {
        cudaFuncSetAttribute(k_qkv_t, cudaFuncAttributeMaxDynamicSharedMemorySize, GEMM_SMEM);
        cudaFuncSetAttribute(k_qk_t,  cudaFuncAttributeMaxDynamicSharedMemorySize, GEMM_SMEM);
        cudaFuncSetAttribute(k_pv_t,  cudaFuncAttributeMaxDynamicSharedMemorySize, GEMM_SMEM);
        cudaFuncSetAttribute(k_out_t, cudaFuncAttributeMaxDynamicSharedMemorySize, GEMM_SMEM);
        attr_done = true;
    }

    k_detect<<<1, 256>>>(mask);
    k_round<<<(NB * NL * ND / 4) / 256, 256>>>(de, en);
    k_transp<<<dim3(32, 32, 4), dim3(32, 8)>>>(Wq, Wk, Wv, Wo);
    k_qkv_t<<<dim3(ND / 128, (NB * NL) / 128, 3), 256, GEMM_SMEM>>>(bq, bk, bv);
    k_qk_t<<<dim3(NL / 128, NL / 128, NZ), 256, GEMM_SMEM>>>(mask);
    k_softmax<<<NZ * NL, 256>>>();
    k_pv_t<<<dim3(1, NL / 128, NZ), 256, GEMM_SMEM>>>();
    k_out_t<<<dim3(ND / 128, (NB * NL) / 128, 1), 256, GEMM_SMEM>>>(bo, de);
    k_ln<<<NB * NL, 256>>>(out, gamma, beta);
}

// round 16
// speedup vs baseline: 1.7849x; 1.7849x over previous
#include <cuda_runtime.h>
#include <cuda_bf16.h>
#include <math.h>
#include <stdint.h>

// Problem constants
#define NB  2
#define NL  2048
#define ND  1024
#define NH  8
#define NHD 128
#define NZ  (NB*NH)   // 16 batched heads

// ---------------- static device scratch ----------------
__device__ __nv_bfloat16 g_Q[(size_t)NZ * NL * NHD];   // [z][l][j]
__device__ __nv_bfloat16 g_K[(size_t)NZ * NL * NHD];   // [z][l][j]
__device__ __nv_bfloat16 g_V[(size_t)NZ * NHD * NL];   // transposed: [z][j][l]
__device__ float         g_S[(size_t)NZ * NL * NL];    // scores (fp32)
__device__ __nv_bfloat16 g_P[(size_t)NZ * NL * NL];    // probs (bf16)
__device__ __nv_bfloat16 g_A[(size_t)NB * NL * ND];    // concat attn out
__device__ float         g_R[(size_t)NB * NL * ND];    // pre-LN result (fp32)
__device__ __nv_bfloat16 g_WT[(size_t)4 * ND * ND];    // W^T [q,k,v,o]
__device__ __nv_bfloat16 g_DE[(size_t)NB * NL * ND];   // bf16 de
__device__ __nv_bfloat16 g_EN[(size_t)NB * NL * ND];   // bf16 en
__device__ int           g_mask_flag;                  // 0=int32, 1=byte, 2=float32

// ---------------- helpers (sm_80+ PTX; legal on compute_103) ----------------
__device__ __forceinline__ void mma_bf16(float* d, const uint32_t* a, const uint32_t* b) {
    asm volatile(
        "mma.sync.aligned.m16n8k16.row.col.f32.bf16.bf16.f32 "
        "{%0,%1,%2,%3}, {%4,%5,%6,%7}, {%8,%9}, {%0,%1,%2,%3};"
        : "+f"(d[0]), "+f"(d[1]), "+f"(d[2]), "+f"(d[3])
        : "r"(a[0]), "r"(a[1]), "r"(a[2]), "r"(a[3]), "r"(b[0]), "r"(b[1]));
}
__device__ __forceinline__ uint32_t smem_u32(const void* p) {
    uint32_t a;
    asm("{ .reg .u64 t; cvta.to.shared.u64 t, %1; cvt.u32.u64 %0, t; }" : "=r"(a) : "l"(p));
    return a;
}
__device__ __forceinline__ void cp16(uint32_t d, const void* s) {
    asm volatile("cp.async.cg.shared.global [%0], [%1], 16;" :: "r"(d), "l"(s));
}
__device__ __forceinline__ void cp_commit() { asm volatile("cp.async.commit_group;" ::: "memory"); }
template<int N> __device__ __forceinline__ void cp_wait() {
    asm volatile("cp.async.wait_group %0;" :: "n"(N) : "memory");
}

// ---------------- shared GEMM core v5: bf16 m16n8k16, 3-stage cp.async ----------
// CTA tile 128x128, BK=32 bf16 (16 uint32 words/row), 128 threads = 4 warps as
// 2(M) x 2(N); warp tile 64x64. One uint32 word = a bf16 k-pair, so fragment
// indexing is identical to the tf32-k8 core, but each instruction carries K=16
// and each tile K=32: half the MMA/LDS/sync count of R14 for the same FLOP.
// Smem rows padded to LDR=20 words (conflict-free permutation, 16B alignment).
#define LDR 20
#define SM_TILE (128 * LDR)                          // uint32 words per operand-stage
#define GEMM_SMEM (3 * 2 * SM_TILE * 4)              // 61440 bytes

__device__ __forceinline__ void gemm_mma(
    const __nv_bfloat16* __restrict__ A, int lda,    // [128+][K] bf16, row-major
    const __nv_bfloat16* __restrict__ B, int ldb,    // [128+][K] bf16, row-major (op-B^T)
    int K, float acc[4][8][4])                       // K in bf16 elements
{
    extern __shared__ uint32_t sm[];                 // [3][2][SM_TILE]
    const int tid  = threadIdx.x;
    const int lane = tid & 31, wid = tid >> 5;
    const int m0 = (wid & 1) * 64, n0 = (wid >> 1) * 64;
    const int gid = lane >> 2, tq = lane & 3;

    const int r0 = tid >> 2;                         // rows 0..31 (+32,+64,+96)
    const int kq = (tid & 3) << 2;                   // word offset in 16-word k slab

    const uint32_t sbase = smem_u32(sm);
    uint32_t soff[4];
    #pragma unroll
    for (int i = 0; i < 4; i++) soff[i] = (uint32_t)(((r0 + 32 * i) * LDR + kq) * 4);

    #pragma unroll
    for (int mt = 0; mt < 4; mt++)
        #pragma unroll
        for (int nt = 0; nt < 8; nt++)
            #pragma unroll
            for (int r = 0; r < 4; r++) acc[mt][nt][r] = 0.0f;

    auto issue = [&](int t, int s) {
        const __nv_bfloat16* Ap = A + (size_t)t * 32 + kq * 2;
        const __nv_bfloat16* Bp = B + (size_t)t * 32 + kq * 2;
        const uint32_t sa = sbase + (uint32_t)(s * 2 * SM_TILE * 4);
        const uint32_t sb = sa + (uint32_t)(SM_TILE * 4);
        #pragma unroll
        for (int i = 0; i < 4; i++) {
            cp16(sa + soff[i], Ap + (size_t)(r0 + 32 * i) * lda);
            cp16(sb + soff[i], Bp + (size_t)(r0 + 32 * i) * ldb);
        }
        cp_commit();
    };

    const int T = K >> 5;                            // BK=32 bf16 per tile
    issue(0, 0);
    if (T > 1) issue(1, 1);

    for (int t = 0; t < T; t++) {
        if (t + 2 < T) cp_wait<1>(); else cp_wait<0>();
        __syncthreads();
        if (t + 2 < T) issue(t + 2, (t + 2) % 3);

        const uint32_t* sAu = sm + (t % 3) * 2 * SM_TILE;
        const uint32_t* sBu = sAu + SM_TILE;

        #pragma unroll
        for (int ks = 0; ks < 16; ks += 8) {         // two K=16 MMA steps per tile
            uint32_t af[4][4], bf[8][2];
            #pragma unroll
            for (int mt = 0; mt < 4; mt++) {
                int mr = m0 + mt * 16 + gid;
                af[mt][0] = sAu[mr * LDR + ks + tq];
                af[mt][1] = sAu[(mr + 8) * LDR + ks + tq];
                af[mt][2] = sAu[mr * LDR + ks + tq + 4];
                af[mt][3] = sAu[(mr + 8) * LDR + ks + tq + 4];
            }
            #pragma unroll
            for (int nt = 0; nt < 8; nt++) {
                int nr = n0 + nt * 8 + gid;
                bf[nt][0] = sBu[nr * LDR + ks + tq];
                bf[nt][1] = sBu[nr * LDR + ks + tq + 4];
            }
            #pragma unroll
            for (int mt = 0; mt < 4; mt++)
                #pragma unroll
                for (int nt = 0; nt < 8; nt++)
                    mma_bf16(acc[mt][nt], af[mt], bf[nt]);
        }
    }
}

// epilogue element mapping:
// row = bm + (wid&1)*64 + mt*16 + gid + hh*8 ; col = bn + (wid>>1)*64 + nt*8 + tq*2 + e
// val = acc[mt][nt][hh*2+e]

// ---------------- mask dtype detection ----------------
__global__ void k_detect(const unsigned char* __restrict__ m) {
    __shared__ int f1, f3;
    if (threadIdx.x == 0) { f1 = 0; f3 = 0; }
    __syncthreads();
    int l1 = 0, l3 = 0;
    const uchar4* m4 = reinterpret_cast<const uchar4*>(m);
    for (int i = threadIdx.x; i < 16384; i += 256) { uchar4 c = m4[i]; l1 |= c.y; l3 |= c.w; }
    if (l1) atomicOr(&f1, 1);
    if (l3) atomicOr(&f3, 1);
    __syncthreads();
    if (threadIdx.x == 0) g_mask_flag = f1 ? 1 : (f3 ? 2 : 0);
}

// ---------------- convert de/en to bf16 copies ----------------
__global__ void k_round(const float* __restrict__ de, const float* __restrict__ en) {
    size_t i = (size_t)blockIdx.x * blockDim.x + threadIdx.x;   // float4 index
    float4 d = ((const float4*)de)[i];
    float4 e = ((const float4*)en)[i];
    __nv_bfloat162* pd = (__nv_bfloat162*)g_DE;
    __nv_bfloat162* pe = (__nv_bfloat162*)g_EN;
    pd[2 * i]     = __float22bfloat162_rn(make_float2(d.x, d.y));
    pd[2 * i + 1] = __float22bfloat162_rn(make_float2(d.z, d.w));
    pe[2 * i]     = __float22bfloat162_rn(make_float2(e.x, e.y));
    pe[2 * i + 1] = __float22bfloat162_rn(make_float2(e.z, e.w));
}

// ---------------- weight transpose (bf16): g_WT[z][out][in] = W[in][out] --------
__global__ void k_transp(const float* __restrict__ W0, const float* __restrict__ W1,
                         const float* __restrict__ W2, const float* __restrict__ W3) {
    __shared__ float t[32][33];
    const int z = blockIdx.z;
    const float* W = (z == 0) ? W0 : (z == 1) ? W1 : (z == 2) ? W2 : W3;
    __nv_bfloat16* O = g_WT + (size_t)z * ND * ND;
    int x = blockIdx.x * 32 + threadIdx.x;
    #pragma unroll
    for (int j = 0; j < 32; j += 8)
        t[threadIdx.y + j][threadIdx.x] = W[(size_t)(blockIdx.y * 32 + threadIdx.y + j) * ND + x];
    __syncthreads();
    int ox = blockIdx.y * 32 + threadIdx.x;
    #pragma unroll
    for (int j = 0; j < 32; j += 8)
        O[(size_t)(blockIdx.x * 32 + threadIdx.y + j) * ND + ox] =
            __float2bfloat16_rn(t[threadIdx.x][threadIdx.y + j]);
}

// ---------------- QKV projections, head-deinterleave epilogue ----------------
__global__ __launch_bounds__(128, 2) void k_qkv_t(
    const float* __restrict__ bq, const float* __restrict__ bk, const float* __restrict__ bv) {
    const int z = blockIdx.z;
    const __nv_bfloat16* X    = (z == 0) ? g_DE : g_EN;
    const float* bias         = (z == 0) ? bq : (z == 1 ? bk : bv);
    const __nv_bfloat16* WT   = g_WT + (size_t)z * ND * ND;
    const int bm = blockIdx.y * 128, bn = blockIdx.x * 128;

    float acc[4][8][4];
    gemm_mma(X + (size_t)bm * ND, ND, WT + (size_t)bn * ND, ND, ND, acc);

    const int lane = threadIdx.x & 31, wid = threadIdx.x >> 5;
    const int m0 = (wid & 1) * 64, n0 = (wid >> 1) * 64;
    const int gid = lane >> 2, tq = lane & 3;
    __nv_bfloat16* qdst = (z == 0) ? g_Q : g_K;
    #pragma unroll
    for (int mt = 0; mt < 4; mt++)
        #pragma unroll
        for (int hh = 0; hh < 2; hh++) {
            int m = bm + m0 + mt * 16 + gid + hh * 8;
            int b = m >> 11, l = m & (NL - 1);
            #pragma unroll
            for (int nt = 0; nt < 8; nt++)
                #pragma unroll
                for (int e = 0; e < 2; e++) {
                    int n = bn + n0 + nt * 8 + tq * 2 + e;
                    __nv_bfloat16 val = __float2bfloat16_rn(acc[mt][nt][hh * 2 + e] + bias[n]);
                    int h = n & 7, jj = n >> 3;    // interleaved split: feature = jj*8+h
                    if (z < 2) qdst[(((size_t)(b * NH + h) * NL + l) << 7) + jj] = val;
                    else       g_V[((size_t)(b * NH + h) * NHD + jj) * NL + l] = val;  // V^T
                }
        }
}

// ---------------- S = Q K^T / 32, masked (fp32 scores out) ----------------
__global__ __launch_bounds__(128, 2) void k_qk_t(const unsigned char* __restrict__ maskraw) {
    const int z = blockIdx.z, b = z >> 3;
    const int bm = blockIdx.y * 128, bn = blockIdx.x * 128;
    const __nv_bfloat16* Qb = g_Q + (size_t)z * NL * NHD;
    const __nv_bfloat16* Kb = g_K + (size_t)z * NL * NHD;

    float acc[4][8][4];
    gemm_mma(Qb + (size_t)bm * NHD, NHD, Kb + (size_t)bn * NHD, NHD, NHD, acc);

    const int lane = threadIdx.x & 31, wid = threadIdx.x >> 5;
    const int m0 = (wid & 1) * 64, n0 = (wid >> 1) * 64;
    const int gid = lane >> 2, tq = lane & 3;
    const int mf = g_mask_flag;
    #pragma unroll
    for (int mt = 0; mt < 4; mt++)
        #pragma unroll
        for (int hh = 0; hh < 2; hh++) {
            int m = bm + m0 + mt * 16 + gid + hh * 8;
            const size_t mrow = ((size_t)b * NL + m) * NL;
            float* srow = g_S + ((size_t)z * NL + m) * NL;
            #pragma unroll
            for (int nt = 0; nt < 8; nt++) {
                int n = bn + n0 + nt * 8 + tq * 2;
                float v0 = acc[mt][nt][hh * 2 + 0] * 0.03125f;   // 1/sqrt(1024)
                float v1 = acc[mt][nt][hh * 2 + 1] * 0.03125f;
                bool k0, k1;
                if (mf == 1) {
                    const unsigned char* mp = maskraw + mrow + n;
                    k0 = mp[0] != 0; k1 = mp[1] != 0;
                } else if (mf == 2) {
                    const float* mp = (const float*)maskraw + mrow + n;
                    k0 = mp[0] != 0.0f; k1 = mp[1] != 0.0f;
                } else {
                    const int* mp = (const int*)maskraw + mrow + n;
                    k0 = mp[0] != 0; k1 = mp[1] != 0;
                }
                float2 o;
                o.x = k0 ? -1e10f : v0;
                o.y = k1 ? -1e10f : v1;
                *(float2*)(srow + n) = o;
            }
        }
}

// ---------------- O = P V, concat-layout epilogue (bf16 out) ----------------
__global__ __launch_bounds__(128, 2) void k_pv_t() {
    const int z = blockIdx.z, b = z >> 3, h = z & 7;
    const int bm = blockIdx.y * 128;
    const __nv_bfloat16* P  = g_P + (size_t)z * NL * NL + (size_t)bm * NL;
    const __nv_bfloat16* Vt = g_V + (size_t)z * NHD * NL;    // [j][l], ld = NL

    float acc[4][8][4];
    gemm_mma(P, NL, Vt, NL, NL, acc);

    const int lane = threadIdx.x & 31, wid = threadIdx.x >> 5;
    const int m0 = (wid & 1) * 64, n0 = (wid >> 1) * 64;
    const int gid = lane >> 2, tq = lane & 3;
    #pragma unroll
    for (int mt = 0; mt < 4; mt++)
        #pragma unroll
        for (int hh = 0; hh < 2; hh++) {
            int m = bm + m0 + mt * 16 + gid + hh * 8;
            __nv_bfloat162* arow = (__nv_bfloat162*)(g_A + ((size_t)b * NL + m) * ND + h * NHD);
            #pragma unroll
            for (int nt = 0; nt < 8; nt++) {
                int n = n0 + nt * 8 + tq * 2;
                arow[n >> 1] = __float22bfloat162_rn(
                    make_float2(acc[mt][nt][hh * 2 + 0], acc[mt][nt][hh * 2 + 1]));
            }
        }
}

// ---------------- R = A Wo + bo + de (residual, fp32 out) ----------------
__global__ __launch_bounds__(128, 2) void k_out_t(const float* __restrict__ bo,
                                                  const float* __restrict__ de) {
    const int bm = blockIdx.y * 128, bn = blockIdx.x * 128;
    const __nv_bfloat16* WoT = g_WT + (size_t)3 * ND * ND;

    float acc[4][8][4];
    gemm_mma(g_A + (size_t)bm * ND, ND, WoT + (size_t)bn * ND, ND, ND, acc);

    const int lane = threadIdx.x & 31, wid = threadIdx.x >> 5;
    const int m0 = (wid & 1) * 64, n0 = (wid >> 1) * 64;
    const int gid = lane >> 2, tq = lane & 3;
    #pragma unroll
    for (int mt = 0; mt < 4; mt++)
        #pragma unroll
        for (int hh = 0; hh < 2; hh++) {
            int m = bm + m0 + mt * 16 + gid + hh * 8;
            const float* drow = de + (size_t)m * ND;
            float* rrow = g_R + (size_t)m * ND;
            #pragma unroll
            for (int nt = 0; nt < 8; nt++) {
                int n = bn + n0 + nt * 8 + tq * 2;
                float2 d2 = *(const float2*)(drow + n);
                float2 b2 = *(const float2*)(bo + n);
                float2 o;
                o.x = acc[mt][nt][hh * 2 + 0] + b2.x + d2.x;
                o.y = acc[mt][nt][hh * 2 + 1] + b2.y + d2.y;
                *(float2*)(rrow + n) = o;
            }
        }
}

// ---------------- block-wide allreduce ----------------
__device__ __forceinline__ float blockAllReduce(float v, bool doMax) {
    __shared__ float sh[8];
    __shared__ float res;
    #pragma unroll
    for (int o = 16; o; o >>= 1) {
        float t = __shfl_xor_sync(0xffffffffu, v, o);
        v = doMax ? fmaxf(v, t) : (v + t);
    }
    if ((threadIdx.x & 31) == 0) sh[threadIdx.x >> 5] = v;
    __syncthreads();
    if (threadIdx.x < 32) {
        float t = (threadIdx.x < 8) ? sh[threadIdx.x] : (doMax ? -INFINITY : 0.0f);
        #pragma unroll
        for (int o = 4; o; o >>= 1) {
            float u = __shfl_xor_sync(0xffffffffu, t, o);
            t = doMax ? fmaxf(t, u) : (t + u);
        }
        if (threadIdx.x == 0) res = t;
    }
    __syncthreads();
    return res;
}

// ---------------- row softmax: fp32 S in, bf16 probs out ----------------
__global__ __launch_bounds__(256) void k_softmax() {
    size_t row = blockIdx.x;
    const float4* p = reinterpret_cast<const float4*>(g_S) + row * (NL / 4);
    float4 a = p[threadIdx.x];
    float4 c = p[threadIdx.x + 256];
    float m = fmaxf(fmaxf(fmaxf(a.x, a.y), fmaxf(a.z, a.w)),
                    fmaxf(fmaxf(c.x, c.y), fmaxf(c.z, c.w)));
    m = blockAllReduce(m, true);
    a.x = __expf(a.x - m); a.y = __expf(a.y - m); a.z = __expf(a.z - m); a.w = __expf(a.w - m);
    c.x = __expf(c.x - m); c.y = __expf(c.y - m); c.z = __expf(c.z - m); c.w = __expf(c.w - m);
    float s = a.x + a.y + a.z + a.w + c.x + c.y + c.z + c.w;
    s = blockAllReduce(s, false);
    float inv = 1.0f / s;
    __nv_bfloat162* prow = reinterpret_cast<__nv_bfloat162*>(g_P + row * NL);
    prow[2 * threadIdx.x]           = __float22bfloat162_rn(make_float2(a.x * inv, a.y * inv));
    prow[2 * threadIdx.x + 1]       = __float22bfloat162_rn(make_float2(a.z * inv, a.w * inv));
    prow[512 + 2 * threadIdx.x]     = __float22bfloat162_rn(make_float2(c.x * inv, c.y * inv));
    prow[512 + 2 * threadIdx.x + 1] = __float22bfloat162_rn(make_float2(c.z * inv, c.w * inv));
}

// ---------------- LayerNorm (ddof=1, eps=1e-8, scalar gamma/beta) ----------------
__global__ __launch_bounds__(256) void k_ln(
    float* __restrict__ out, const float* __restrict__ gamma, const float* __restrict__ beta) {
    size_t row = blockIdx.x;
    const float4* x4 = reinterpret_cast<const float4*>(g_R) + row * (ND / 4);
    float4 v = x4[threadIdx.x];
    float s  = v.x + v.y + v.z + v.w;
    float ss = v.x * v.x + v.y * v.y + v.z * v.z + v.w * v.w;
    s  = blockAllReduce(s,  false);
    ss = blockAllReduce(ss, false);
    float mu  = s * (1.0f / 1024.0f);
    float var = (ss - 1024.0f * mu * mu) * (1.0f / 1023.0f);
    float w = rsqrtf(var + 1e-8f);
    float g = gamma[0] * w, bb = beta[0];
    float4 o;
    o.x = (v.x - mu) * g + bb;
    o.y = (v.y - mu) * g + bb;
    o.z = (v.z - mu) * g + bb;
    o.w = (v.w - mu) * g + bb;
    reinterpret_cast<float4*>(out)[row * (ND / 4) + threadIdx.x] = o;
}

// ---------------- launch ----------------
extern "C" void kernel_launch(void* const* d_in, const int* in_sizes, int n_in,
                              void* d_out, int out_size) {
    (void)in_sizes; (void)n_in; (void)out_size;
    const float* en = (const float*)d_in[0];
    const float* de = (const float*)d_in[1];
    const unsigned char* mask = (const unsigned char*)d_in[2];
    const float* Wq = (const float*)d_in[3];
    const float* bq = (const float*)d_in[4];
    const float* Wk = (const float*)d_in[5];
    const float* bk = (const float*)d_in[6];
    const float* Wv = (const float*)d_in[7];
    const float* bv = (const float*)d_in[8];
    const float* Wo = (const float*)d_in[9];
    const float* bo = (const float*)d_in[10];
    const float* gamma = (const float*)d_in[11];
    const float* beta  = (const float*)d_in[12];
    float* out = (float*)d_out;

    static bool attr_done = false;
    if (!attr_done) {
        cudaFuncSetAttribute(k_qkv_t, cudaFuncAttributeMaxDynamicSharedMemorySize, GEMM_SMEM);
        cudaFuncSetAttribute(k_qk_t,  cudaFuncAttributeMaxDynamicSharedMemorySize, GEMM_SMEM);
        cudaFuncSetAttribute(k_pv_t,  cudaFuncAttributeMaxDynamicSharedMemorySize, GEMM_SMEM);
        cudaFuncSetAttribute(k_out_t, cudaFuncAttributeMaxDynamicSharedMemorySize, GEMM_SMEM);
        attr_done = true;
    }

    k_detect<<<1, 256>>>(mask);
    k_round<<<(NB * NL * ND / 4) / 256, 256>>>(de, en);
    k_transp<<<dim3(32, 32, 4), dim3(32, 8)>>>(Wq, Wk, Wv, Wo);
    k_qkv_t<<<dim3(ND / 128, (NB * NL) / 128, 3), 128, GEMM_SMEM>>>(bq, bk, bv);
    k_qk_t<<<dim3(NL / 128, NL / 128, NZ), 128, GEMM_SMEM>>>(mask);
    k_softmax<<<NZ * NL, 256>>>();
    k_pv_t<<<dim3(1, NL / 128, NZ), 128, GEMM_SMEM>>>();
    k_out_t<<<dim3(ND / 128, (NB * NL) / 128, 1), 128, GEMM_SMEM>>>(bo, de);
    k_ln<<<NB * NL, 256>>>(out, gamma, beta);
}

// round 17
// speedup vs baseline: 1.8367x; 1.0290x over previous
#include <cuda_runtime.h>
#include <cuda_bf16.h>
#include <math.h>
#include <stdint.h>

// Problem constants
#define NB  2
#define NL  2048
#define ND  1024
#define NH  8
#define NHD 128
#define NZ  (NB*NH)   // 16 batched heads

// ---------------- static device scratch ----------------
__device__ __nv_bfloat16 g_Q[(size_t)NZ * NL * NHD];   // [z][l][j]
__device__ __nv_bfloat16 g_K[(size_t)NZ * NL * NHD];   // [z][l][j]
__device__ __nv_bfloat16 g_V[(size_t)NZ * NHD * NL];   // transposed: [z][j][l]
__device__ float         g_S[(size_t)NZ * NL * NL];    // scores (fp32)
__device__ __nv_bfloat16 g_P[(size_t)NZ * NL * NL];    // probs (bf16)
__device__ __nv_bfloat16 g_A[(size_t)NB * NL * ND];    // concat attn out
__device__ float         g_R[(size_t)NB * NL * ND];    // pre-LN result (fp32)
__device__ __nv_bfloat16 g_WT[(size_t)4 * ND * ND];    // W^T [q,k,v,o]
__device__ __nv_bfloat16 g_DE[(size_t)NB * NL * ND];   // bf16 de
__device__ __nv_bfloat16 g_EN[(size_t)NB * NL * ND];   // bf16 en
__device__ int           g_mask_flag;                  // 0=int32, 1=byte, 2=float32

// ---------------- helpers (sm_75/80+ PTX; legal on compute_103) ----------------
__device__ __forceinline__ void mma_bf16(float* d, const uint32_t* a, const uint32_t* b) {
    asm volatile(
        "mma.sync.aligned.m16n8k16.row.col.f32.bf16.bf16.f32 "
        "{%0,%1,%2,%3}, {%4,%5,%6,%7}, {%8,%9}, {%0,%1,%2,%3};"
        : "+f"(d[0]), "+f"(d[1]), "+f"(d[2]), "+f"(d[3])
        : "r"(a[0]), "r"(a[1]), "r"(a[2]), "r"(a[3]), "r"(b[0]), "r"(b[1]));
}
__device__ __forceinline__ void ldsm_x4(uint32_t* r, uint32_t addr) {
    asm volatile("ldmatrix.sync.aligned.m8n8.x4.shared.b16 {%0,%1,%2,%3}, [%4];"
        : "=r"(r[0]), "=r"(r[1]), "=r"(r[2]), "=r"(r[3]) : "r"(addr));
}
__device__ __forceinline__ uint32_t smem_u32(const void* p) {
    uint32_t a;
    asm("{ .reg .u64 t; cvta.to.shared.u64 t, %1; cvt.u32.u64 %0, t; }" : "=r"(a) : "l"(p));
    return a;
}
__device__ __forceinline__ void cp16(uint32_t d, const void* s) {
    asm volatile("cp.async.cg.shared.global [%0], [%1], 16;" :: "r"(d), "l"(s));
}
__device__ __forceinline__ void cp_commit() { asm volatile("cp.async.commit_group;" ::: "memory"); }
template<int N> __device__ __forceinline__ void cp_wait() {
    asm volatile("cp.async.wait_group %0;" :: "n"(N) : "memory");
}

// ---------------- shared GEMM core v6: bf16 k16 + ldmatrix fragments ------------
// CTA tile 128x128, BK=32 bf16 (16 words/row), 128 threads = 4 warps 2(M)x2(N),
// warp tile 64x64. Fragment loads via ldmatrix.x4: per warp k-step 8 LDSM replace
// 32 scalar LDS (R16's issue-bound hotspot). LDR=20 padding: 80B row stride puts
// 8 consecutive rows at distinct 16B slots mod 128B -> ldmatrix conflict-free.
// A-frag x4 matrices: rows0-7/k0-7, rows8-15/k0-7, rows0-7/k8-15, rows8-15/k8-15
//   lane addr: row=(lane&15), word=ks+((lane>>4)<<2)
// B-frag x4 = two nt:  (nt rows, w0),(nt rows, w4),(nt+1 rows, w0),(nt+1 rows, w4)
//   lane addr: row=(lane&7)+((lane>>4)<<3), word=ks+(((lane>>3)&1)<<2)
#define LDR 20
#define SM_TILE (128 * LDR)                          // uint32 words per operand-stage
#define GEMM_SMEM (3 * 2 * SM_TILE * 4)              // 61440 bytes

__device__ __forceinline__ void gemm_mma(
    const __nv_bfloat16* __restrict__ A, int lda,    // [128+][K] bf16, row-major
    const __nv_bfloat16* __restrict__ B, int ldb,    // [128+][K] bf16, row-major (op-B^T)
    int K, float acc[4][8][4])                       // K in bf16 elements
{
    extern __shared__ uint32_t sm[];                 // [3][2][SM_TILE]
    const int tid  = threadIdx.x;
    const int lane = tid & 31, wid = tid >> 5;
    const int m0 = (wid & 1) * 64, n0 = (wid >> 1) * 64;

    const int r0 = tid >> 2;                         // rows 0..31 (+32,+64,+96)
    const int kq = (tid & 3) << 2;                   // word offset in 16-word k slab

    const uint32_t sbase = smem_u32(sm);
    uint32_t soff[4];
    #pragma unroll
    for (int i = 0; i < 4; i++) soff[i] = (uint32_t)(((r0 + 32 * i) * LDR + kq) * 4);

    // ldmatrix lane-address components (bytes, relative to operand stage base)
    const uint32_t aRow0 = (uint32_t)(((m0 + (lane & 15)) * LDR + ((lane >> 4) << 2)) * 4);
    const uint32_t bRow0 = (uint32_t)(((n0 + (lane & 7) + ((lane >> 4) << 3)) * LDR
                                       + (((lane >> 3) & 1) << 2)) * 4);

    #pragma unroll
    for (int mt = 0; mt < 4; mt++)
        #pragma unroll
        for (int nt = 0; nt < 8; nt++)
            #pragma unroll
            for (int r = 0; r < 4; r++) acc[mt][nt][r] = 0.0f;

    auto issue = [&](int t, int s) {
        const __nv_bfloat16* Ap = A + (size_t)t * 32 + kq * 2;
        const __nv_bfloat16* Bp = B + (size_t)t * 32 + kq * 2;
        const uint32_t sa = sbase + (uint32_t)(s * 2 * SM_TILE * 4);
        const uint32_t sb = sa + (uint32_t)(SM_TILE * 4);
        #pragma unroll
        for (int i = 0; i < 4; i++) {
            cp16(sa + soff[i], Ap + (size_t)(r0 + 32 * i) * lda);
            cp16(sb + soff[i], Bp + (size_t)(r0 + 32 * i) * ldb);
        }
        cp_commit();
    };

    const int T = K >> 5;                            // BK=32 bf16 per tile
    issue(0, 0);
    if (T > 1) issue(1, 1);

    for (int t = 0; t < T; t++) {
        if (t + 2 < T) cp_wait<1>(); else cp_wait<0>();
        __syncthreads();
        if (t + 2 < T) issue(t + 2, (t + 2) % 3);

        const uint32_t stageA = sbase + (uint32_t)((t % 3) * 2 * SM_TILE * 4);
        const uint32_t stageB = stageA + (uint32_t)(SM_TILE * 4);

        #pragma unroll
        for (int ks = 0; ks < 16; ks += 8) {         // two K=16 MMA steps per tile
            uint32_t af[4][4], bf[8][2];
            #pragma unroll
            for (int mt = 0; mt < 4; mt++)
                ldsm_x4(af[mt], stageA + aRow0 + (uint32_t)(mt * 16 * LDR * 4 + ks * 4));
            #pragma unroll
            for (int p = 0; p < 4; p++) {
                uint32_t r[4];
                ldsm_x4(r, stageB + bRow0 + (uint32_t)(p * 16 * LDR * 4 + ks * 4));
                bf[2 * p][0] = r[0]; bf[2 * p][1] = r[1];
                bf[2 * p + 1][0] = r[2]; bf[2 * p + 1][1] = r[3];
            }
            #pragma unroll
            for (int mt = 0; mt < 4; mt++)
                #pragma unroll
                for (int nt = 0; nt < 8; nt++)
                    mma_bf16(acc[mt][nt], af[mt], bf[nt]);
        }
    }
}

// epilogue element mapping:
// row = bm + (wid&1)*64 + mt*16 + gid + hh*8 ; col = bn + (wid>>1)*64 + nt*8 + tq*2 + e
// val = acc[mt][nt][hh*2+e]

// ---------------- mask dtype detection ----------------
__global__ void k_detect(const unsigned char* __restrict__ m) {
    __shared__ int f1, f3;
    if (threadIdx.x == 0) { f1 = 0; f3 = 0; }
    __syncthreads();
    int l1 = 0, l3 = 0;
    const uchar4* m4 = reinterpret_cast<const uchar4*>(m);
    for (int i = threadIdx.x; i < 16384; i += 256) { uchar4 c = m4[i]; l1 |= c.y; l3 |= c.w; }
    if (l1) atomicOr(&f1, 1);
    if (l3) atomicOr(&f3, 1);
    __syncthreads();
    if (threadIdx.x == 0) g_mask_flag = f1 ? 1 : (f3 ? 2 : 0);
}

// ---------------- convert de/en to bf16 copies ----------------
__global__ void k_round(const float* __restrict__ de, const float* __restrict__ en) {
    size_t i = (size_t)blockIdx.x * blockDim.x + threadIdx.x;   // float4 index
    float4 d = ((const float4*)de)[i];
    float4 e = ((const float4*)en)[i];
    __nv_bfloat162* pd = (__nv_bfloat162*)g_DE;
    __nv_bfloat162* pe = (__nv_bfloat162*)g_EN;
    pd[2 * i]     = __float22bfloat162_rn(make_float2(d.x, d.y));
    pd[2 * i + 1] = __float22bfloat162_rn(make_float2(d.z, d.w));
    pe[2 * i]     = __float22bfloat162_rn(make_float2(e.x, e.y));
    pe[2 * i + 1] = __float22bfloat162_rn(make_float2(e.z, e.w));
}

// ---------------- weight transpose (bf16): g_WT[z][out][in] = W[in][out] --------
__global__ void k_transp(const float* __restrict__ W0, const float* __restrict__ W1,
                         const float* __restrict__ W2, const float* __restrict__ W3) {
    __shared__ float t[32][33];
    const int z = blockIdx.z;
    const float* W = (z == 0) ? W0 : (z == 1) ? W1 : (z == 2) ? W2 : W3;
    __nv_bfloat16* O = g_WT + (size_t)z * ND * ND;
    int x = blockIdx.x * 32 + threadIdx.x;
    #pragma unroll
    for (int j = 0; j < 32; j += 8)
        t[threadIdx.y + j][threadIdx.x] = W[(size_t)(blockIdx.y * 32 + threadIdx.y + j) * ND + x];
    __syncthreads();
    int ox = blockIdx.y * 32 + threadIdx.x;
    #pragma unroll
    for (int j = 0; j < 32; j += 8)
        O[(size_t)(blockIdx.x * 32 + threadIdx.y + j) * ND + ox] =
            __float2bfloat16_rn(t[threadIdx.x][threadIdx.y + j]);
}

// ---------------- QKV projections, head-deinterleave epilogue ----------------
__global__ __launch_bounds__(128, 2) void k_qkv_t(
    const float* __restrict__ bq, const float* __restrict__ bk, const float* __restrict__ bv) {
    const int z = blockIdx.z;
    const __nv_bfloat16* X    = (z == 0) ? g_DE : g_EN;
    const float* bias         = (z == 0) ? bq : (z == 1 ? bk : bv);
    const __nv_bfloat16* WT   = g_WT + (size_t)z * ND * ND;
    const int bm = blockIdx.y * 128, bn = blockIdx.x * 128;

    float acc[4][8][4];
    gemm_mma(X + (size_t)bm * ND, ND, WT + (size_t)bn * ND, ND, ND, acc);

    const int lane = threadIdx.x & 31, wid = threadIdx.x >> 5;
    const int m0 = (wid & 1) * 64, n0 = (wid >> 1) * 64;
    const int gid = lane >> 2, tq = lane & 3;
    __nv_bfloat16* qdst = (z == 0) ? g_Q : g_K;
    #pragma unroll
    for (int mt = 0; mt < 4; mt++)
        #pragma unroll
        for (int hh = 0; hh < 2; hh++) {
            int m = bm + m0 + mt * 16 + gid + hh * 8;
            int b = m >> 11, l = m & (NL - 1);
            #pragma unroll
            for (int nt = 0; nt < 8; nt++)
                #pragma unroll
                for (int e = 0; e < 2; e++) {
                    int n = bn + n0 + nt * 8 + tq * 2 + e;
                    __nv_bfloat16 val = __float2bfloat16_rn(acc[mt][nt][hh * 2 + e] + bias[n]);
                    int h = n & 7, jj = n >> 3;    // interleaved split: feature = jj*8+h
                    if (z < 2) qdst[(((size_t)(b * NH + h) * NL + l) << 7) + jj] = val;
                    else       g_V[((size_t)(b * NH + h) * NHD + jj) * NL + l] = val;  // V^T
                }
        }
}

// ---------------- S = Q K^T / 32, masked (fp32 scores out) ----------------
__global__ __launch_bounds__(128, 2) void k_qk_t(const unsigned char* __restrict__ maskraw) {
    const int z = blockIdx.z, b = z >> 3;
    const int bm = blockIdx.y * 128, bn = blockIdx.x * 128;
    const __nv_bfloat16* Qb = g_Q + (size_t)z * NL * NHD;
    const __nv_bfloat16* Kb = g_K + (size_t)z * NL * NHD;

    float acc[4][8][4];
    gemm_mma(Qb + (size_t)bm * NHD, NHD, Kb + (size_t)bn * NHD, NHD, NHD, acc);

    const int lane = threadIdx.x & 31, wid = threadIdx.x >> 5;
    const int m0 = (wid & 1) * 64, n0 = (wid >> 1) * 64;
    const int gid = lane >> 2, tq = lane & 3;
    const int mf = g_mask_flag;
    #pragma unroll
    for (int mt = 0; mt < 4; mt++)
        #pragma unroll
        for (int hh = 0; hh < 2; hh++) {
            int m = bm + m0 + mt * 16 + gid + hh * 8;
            const size_t mrow = ((size_t)b * NL + m) * NL;
            float* srow = g_S + ((size_t)z * NL + m) * NL;
            #pragma unroll
            for (int nt = 0; nt < 8; nt++) {
                int n = bn + n0 + nt * 8 + tq * 2;
                float v0 = acc[mt][nt][hh * 2 + 0] * 0.03125f;   // 1/sqrt(1024)
                float v1 = acc[mt][nt][hh * 2 + 1] * 0.03125f;
                bool k0, k1;
                if (mf == 1) {
                    const unsigned char* mp = maskraw + mrow + n;
                    k0 = mp[0] != 0; k1 = mp[1] != 0;
                } else if (mf == 2) {
                    const float* mp = (const float*)maskraw + mrow + n;
                    k0 = mp[0] != 0.0f; k1 = mp[1] != 0.0f;
                } else {
                    const int* mp = (const int*)maskraw + mrow + n;
                    k0 = mp[0] != 0; k1 = mp[1] != 0;
                }
                float2 o;
                o.x = k0 ? -1e10f : v0;
                o.y = k1 ? -1e10f : v1;
                *(float2*)(srow + n) = o;
            }
        }
}

// ---------------- O = P V, concat-layout epilogue (bf16 out) ----------------
__global__ __launch_bounds__(128, 2) void k_pv_t() {
    const int z = blockIdx.z, b = z >> 3, h = z & 7;
    const int bm = blockIdx.y * 128;
    const __nv_bfloat16* P  = g_P + (size_t)z * NL * NL + (size_t)bm * NL;
    const __nv_bfloat16* Vt = g_V + (size_t)z * NHD * NL;    // [j][l], ld = NL

    float acc[4][8][4];
    gemm_mma(P, NL, Vt, NL, NL, acc);

    const int lane = threadIdx.x & 31, wid = threadIdx.x >> 5;
    const int m0 = (wid & 1) * 64, n0 = (wid >> 1) * 64;
    const int gid = lane >> 2, tq = lane & 3;
    #pragma unroll
    for (int mt = 0; mt < 4; mt++)
        #pragma unroll
        for (int hh = 0; hh < 2; hh++) {
            int m = bm + m0 + mt * 16 + gid + hh * 8;
            __nv_bfloat162* arow = (__nv_bfloat162*)(g_A + ((size_t)b * NL + m) * ND + h * NHD);
            #pragma unroll
            for (int nt = 0; nt < 8; nt++) {
                int n = n0 + nt * 8 + tq * 2;
                arow[n >> 1] = __float22bfloat162_rn(
                    make_float2(acc[mt][nt][hh * 2 + 0], acc[mt][nt][hh * 2 + 1]));
            }
        }
}

// ---------------- R = A Wo + bo + de (residual, fp32 out) ----------------
__global__ __launch_bounds__(128, 2) void k_out_t(const float* __restrict__ bo,
                                                  const float* __restrict__ de) {
    const int bm = blockIdx.y * 128, bn = blockIdx.x * 128;
    const __nv_bfloat16* WoT = g_WT + (size_t)3 * ND * ND;

    float acc[4][8][4];
    gemm_mma(g_A + (size_t)bm * ND, ND, WoT + (size_t)bn * ND, ND, ND, acc);

    const int lane = threadIdx.x & 31, wid = threadIdx.x >> 5;
    const int m0 = (wid & 1) * 64, n0 = (wid >> 1) * 64;
    const int gid = lane >> 2, tq = lane & 3;
    #pragma unroll
    for (int mt = 0; mt < 4; mt++)
        #pragma unroll
        for (int hh = 0; hh < 2; hh++) {
            int m = bm + m0 + mt * 16 + gid + hh * 8;
            const float* drow = de + (size_t)m * ND;
            float* rrow = g_R + (size_t)m * ND;
            #pragma unroll
            for (int nt = 0; nt < 8; nt++) {
                int n = bn + n0 + nt * 8 + tq * 2;
                float2 d2 = *(const float2*)(drow + n);
                float2 b2 = *(const float2*)(bo + n);
                float2 o;
                o.x = acc[mt][nt][hh * 2 + 0] + b2.x + d2.x;
                o.y = acc[mt][nt][hh * 2 + 1] + b2.y + d2.y;
                *(float2*)(rrow + n) = o;
            }
        }
}

// ---------------- block-wide allreduce ----------------
__device__ __forceinline__ float blockAllReduce(float v, bool doMax) {
    __shared__ float sh[8];
    __shared__ float res;
    #pragma unroll
    for (int o = 16; o; o >>= 1) {
        float t = __shfl_xor_sync(0xffffffffu, v, o);
        v = doMax ? fmaxf(v, t) : (v + t);
    }
    if ((threadIdx.x & 31) == 0) sh[threadIdx.x >> 5] = v;
    __syncthreads();
    if (threadIdx.x < 32) {
        float t = (threadIdx.x < 8) ? sh[threadIdx.x] : (doMax ? -INFINITY : 0.0f);
        #pragma unroll
        for (int o = 4; o; o >>= 1) {
            float u = __shfl_xor_sync(0xffffffffu, t, o);
            t = doMax ? fmaxf(t, u) : (t + u);
        }
        if (threadIdx.x == 0) res = t;
    }
    __syncthreads();
    return res;
}

// ---------------- row softmax: fp32 S in, bf16 probs out ----------------
__global__ __launch_bounds__(256) void k_softmax() {
    size_t row = blockIdx.x;
    const float4* p = reinterpret_cast<const float4*>(g_S) + row * (NL / 4);
    float4 a = p[threadIdx.x];
    float4 c = p[threadIdx.x + 256];
    float m = fmaxf(fmaxf(fmaxf(a.x, a.y), fmaxf(a.z, a.w)),
                    fmaxf(fmaxf(c.x, c.y), fmaxf(c.z, c.w)));
    m = blockAllReduce(m, true);
    a.x = __expf(a.x - m); a.y = __expf(a.y - m); a.z = __expf(a.z - m); a.w = __expf(a.w - m);
    c.x = __expf(c.x - m); c.y = __expf(c.y - m); c.z = __expf(c.z - m); c.w = __expf(c.w - m);
    float s = a.x + a.y + a.z + a.w + c.x + c.y + c.z + c.w;
    s = blockAllReduce(s, false);
    float inv = 1.0f / s;
    __nv_bfloat162* prow = reinterpret_cast<__nv_bfloat162*>(g_P + row * NL);
    prow[2 * threadIdx.x]           = __float22bfloat162_rn(make_float2(a.x * inv, a.y * inv));
    prow[2 * threadIdx.x + 1]       = __float22bfloat162_rn(make_float2(a.z * inv, a.w * inv));
    prow[512 + 2 * threadIdx.x]     = __float22bfloat162_rn(make_float2(c.x * inv, c.y * inv));
    prow[512 + 2 * threadIdx.x + 1] = __float22bfloat162_rn(make_float2(c.z * inv, c.w * inv));
}

// ---------------- LayerNorm (ddof=1, eps=1e-8, scalar gamma/beta) ----------------
__global__ __launch_bounds__(256) void k_ln(
    float* __restrict__ out, const float* __restrict__ gamma, const float* __restrict__ beta) {
    size_t row = blockIdx.x;
    const float4* x4 = reinterpret_cast<const float4*>(g_R) + row * (ND / 4);
    float4 v = x4[threadIdx.x];
    float s  = v.x + v.y + v.z + v.w;
    float ss = v.x * v.x + v.y * v.y + v.z * v.z + v.w * v.w;
    s  = blockAllReduce(s,  false);
    ss = blockAllReduce(ss, false);
    float mu  = s * (1.0f / 1024.0f);
    float var = (ss - 1024.0f * mu * mu) * (1.0f / 1023.0f);
    float w = rsqrtf(var + 1e-8f);
    float g = gamma[0] * w, bb = beta[0];
    float4 o;
    o.x = (v.x - mu) * g + bb;
    o.y = (v.y - mu) * g + bb;
    o.z = (v.z - mu) * g + bb;
    o.w = (v.w - mu) * g + bb;
    reinterpret_cast<float4*>(out)[row * (ND / 4) + threadIdx.x] = o;
}

// ---------------- launch ----------------
extern "C" void kernel_launch(void* const* d_in, const int* in_sizes, int n_in,
                              void* d_out, int out_size) {
    (void)in_sizes; (void)n_in; (void)out_size;
    const float* en = (const float*)d_in[0];
    const float* de = (const float*)d_in[1];
    const unsigned char* mask = (const unsigned char*)d_in[2];
    const float* Wq = (const float*)d_in[3];
    const float* bq = (const float*)d_in[4];
    const float* Wk = (const float*)d_in[5];
    const float* bk = (const float*)d_in[6];
    const float* Wv = (const float*)d_in[7];
    const float* bv = (const float*)d_in[8];
    const float* Wo = (const float*)d_in[9];
    const float* bo = (const float*)d_in[10];
    const float* gamma = (const float*)d_in[11];
    const float* beta  = (const float*)d_in[12];
    float* out = (float*)d_out;

    static bool attr_done = false;
    if (!attr_done) {
        cudaFuncSetAttribute(k_qkv_t, cudaFuncAttributeMaxDynamicSharedMemorySize, GEMM_SMEM);
        cudaFuncSetAttribute(k_qk_t,  cudaFuncAttributeMaxDynamicSharedMemorySize, GEMM_SMEM);
        cudaFuncSetAttribute(k_pv_t,  cudaFuncAttributeMaxDynamicSharedMemorySize, GEMM_SMEM);
        cudaFuncSetAttribute(k_out_t, cudaFuncAttributeMaxDynamicSharedMemorySize, GEMM_SMEM);
        attr_done = true;
    }

    k_detect<<<1, 256>>>(mask);
    k_round<<<(NB * NL * ND / 4) / 256, 256>>>(de, en);
    k_transp<<<dim3(32, 32, 4), dim3(32, 8)>>>(Wq, Wk, Wv, Wo);
    k_qkv_t<<<dim3(ND / 128, (NB * NL) / 128, 3), 128, GEMM_SMEM>>>(bq, bk, bv);
    k_qk_t<<<dim3(NL / 128, NL / 128, NZ), 128, GEMM_SMEM>>>(mask);
    k_softmax<<<NZ * NL, 256>>>();
    k_pv_t<<<dim3(1, NL / 128, NZ), 128, GEMM_SMEM>>>();
    k_out_t<<<dim3(ND / 128, (NB * NL) / 128, 1), 128, GEMM_SMEM>>>(bo, de);
    k_ln<<<NB * NL, 256>>>(out, gamma, beta);
}